// round 1
// baseline (speedup 1.0000x reference)
#include <cuda_runtime.h>
#include <math.h>

#define LQ 2048
#define DMODEL 3072
#define NHEAD 24
#define HDIM 128
#define MLPD 12288
#define N1 21504   // 3*D + MLP
#define DM 15360   // D + MLP
#define TD3 9216   // 3*D

// ---------------- scratch (device globals; no allocation allowed) ----------------
__device__ float g_mod[3 * DMODEL];          // [shift | scale | gate]
__device__ float g_xmod[(size_t)LQ * DMODEL];
__device__ float g_q[(size_t)NHEAD * LQ * HDIM];
__device__ float g_k[(size_t)NHEAD * LQ * HDIM];
__device__ float g_v[(size_t)NHEAD * LQ * HDIM];
__device__ float g_scr[(size_t)LQ * DM];     // [attn | gelu(mlp)]

// ---------------- K0: mod = silu(vec) @ mod_w + mod_b ----------------
__global__ void k_mod(const float* __restrict__ vec,
                      const float* __restrict__ mod_w,
                      const float* __restrict__ mod_b) {
    __shared__ float sv[DMODEL];
    for (int i = threadIdx.x; i < DMODEL; i += blockDim.x) {
        float v = vec[i];
        sv[i] = v / (1.0f + expf(-v));
    }
    __syncthreads();
    int col = blockIdx.x * 256 + threadIdx.x;
    float acc = 0.f;
    for (int i = 0; i < DMODEL; ++i)
        acc = fmaf(sv[i], mod_w[(size_t)i * (3 * DMODEL) + col], acc);
    g_mod[col] = acc + mod_b[col];
}

// ---------------- block reduce helper (256 threads) ----------------
__device__ __forceinline__ float block_sum_256(float v, float* red8) {
    #pragma unroll
    for (int o = 16; o > 0; o >>= 1) v += __shfl_xor_sync(0xffffffffu, v, o);
    if ((threadIdx.x & 31) == 0) red8[threadIdx.x >> 5] = v;
    __syncthreads();
    float t = 0.f;
    #pragma unroll
    for (int i = 0; i < 8; ++i) t += red8[i];
    __syncthreads();
    return t;
}

// ---------------- K1: x_mod = shift + (1+scale)*layer_norm(x) ----------------
__global__ void k_xmod(const float* __restrict__ x) {
    __shared__ float red8[8];
    int t = blockIdx.x;
    const float* xr = x + (size_t)t * DMODEL;
    float s = 0.f;
    for (int i = threadIdx.x; i < DMODEL; i += 256) s += xr[i];
    float mu = block_sum_256(s, red8) * (1.0f / DMODEL);
    float vs = 0.f;
    for (int i = threadIdx.x; i < DMODEL; i += 256) {
        float d = xr[i] - mu;
        vs += d * d;
    }
    float var = block_sum_256(vs, red8) * (1.0f / DMODEL);
    float rstd = rsqrtf(var + 1e-6f);
    float* dst = g_xmod + (size_t)t * DMODEL;
    for (int i = threadIdx.x; i < DMODEL; i += 256) {
        float ln = (xr[i] - mu) * rstd;
        dst[i] = g_mod[i] + (1.0f + g_mod[DMODEL + i]) * ln;
    }
}

// ---------------- K2: GEMM1  h = g_xmod @ w1 + b1, routed epilogue ----------------
__global__ __launch_bounds__(256, 2) void k_gemm1(const float* __restrict__ Bm,
                                                  const float* __restrict__ b1) {
    __shared__ __align__(16) float sA[16][132];
    __shared__ __align__(16) float sB[16][128];
    const int K = DMODEL, N = N1;
    const float* A = g_xmod;
    int tid = threadIdx.x;
    int m0 = blockIdx.y * 128, n0 = blockIdx.x * 128;
    int rr2 = (tid >> 4) * 4, cc2 = (tid & 15) * 4;
    float acc[8][8];
    #pragma unroll
    for (int i = 0; i < 8; i++)
        #pragma unroll
        for (int j = 0; j < 8; j++) acc[i][j] = 0.f;

    int ar = tid >> 2, ac = (tid & 3) * 4;
    int br = tid >> 5, bc = (tid & 31) * 4;
    const float* Aptr = A + (size_t)(m0 + ar) * K + ac;
    const float* Bptr = Bm + (size_t)br * N + n0 + bc;

    for (int k0 = 0; k0 < K; k0 += 16) {
        float4 a0 = *(const float4*)(Aptr);
        float4 a1 = *(const float4*)(Aptr + (size_t)64 * K);
        float4 bb0 = *(const float4*)(Bptr);
        float4 bb1 = *(const float4*)(Bptr + (size_t)8 * N);
        sA[ac + 0][ar] = a0.x; sA[ac + 1][ar] = a0.y;
        sA[ac + 2][ar] = a0.z; sA[ac + 3][ar] = a0.w;
        sA[ac + 0][ar + 64] = a1.x; sA[ac + 1][ar + 64] = a1.y;
        sA[ac + 2][ar + 64] = a1.z; sA[ac + 3][ar + 64] = a1.w;
        *(float4*)&sB[br][bc] = bb0;
        *(float4*)&sB[br + 8][bc] = bb1;
        __syncthreads();
        #pragma unroll
        for (int kk = 0; kk < 16; kk++) {
            float a[8], b[8];
            *(float4*)(a) = *(const float4*)&sA[kk][rr2];
            *(float4*)(a + 4) = *(const float4*)&sA[kk][64 + rr2];
            *(float4*)(b) = *(const float4*)&sB[kk][cc2];
            *(float4*)(b + 4) = *(const float4*)&sB[kk][64 + cc2];
            #pragma unroll
            for (int i = 0; i < 8; i++)
                #pragma unroll
                for (int j = 0; j < 8; j++)
                    acc[i][j] = fmaf(a[i], b[j], acc[i][j]);
        }
        __syncthreads();
        Aptr += 16;
        Bptr += (size_t)16 * N;
    }

    // epilogue: route qkv / gelu(mlp). n0 is a multiple of 128 so the whole
    // block tile sits in one (which, head) chunk or wholly in mlp.
    bool is_qkv = n0 < TD3;
    float* qkvdst = nullptr;
    if (is_qkv) {
        int which = n0 / DMODEL;
        int head = (n0 % DMODEL) / HDIM;
        float* base = (which == 0) ? g_q : (which == 1) ? g_k : g_v;
        qkvdst = base + (size_t)head * LQ * HDIM;
    }
    #pragma unroll
    for (int i = 0; i < 8; i++) {
        int m = m0 + rr2 + ((i < 4) ? i : 64 + i - 4);
        #pragma unroll
        for (int j = 0; j < 8; j++) {
            int dcol = cc2 + ((j < 4) ? j : 64 + j - 4);
            int n = n0 + dcol;
            float val = acc[i][j] + b1[n];
            if (is_qkv) {
                qkvdst[(size_t)m * HDIM + dcol] = val;
            } else {
                float x3 = val * val * val;
                float g = 0.5f * val *
                          (1.f + tanhf(0.7978845608028654f * (val + 0.044715f * x3)));
                g_scr[(size_t)m * DM + DMODEL + (n - TD3)] = g;
            }
        }
    }
}

// ---------------- K3: rms_norm + rope on q and k ----------------
__global__ void k_rmsrope(const float* __restrict__ pe,
                          const float* __restrict__ q_scale,
                          const float* __restrict__ k_scale) {
    int t = blockIdx.x, h = blockIdx.y, qk = blockIdx.z;
    float* buf = (qk == 0 ? g_q : g_k) + ((size_t)h * LQ + t) * HDIM;
    const float* sc = (qk == 0) ? q_scale : k_scale;
    int d = threadIdx.x;
    float v = buf[d];
    __shared__ float red[4];
    __shared__ float sv[HDIM];
    float ss = v * v;
    #pragma unroll
    for (int o = 16; o > 0; o >>= 1) ss += __shfl_xor_sync(0xffffffffu, ss, o);
    if ((d & 31) == 0) red[d >> 5] = ss;
    __syncthreads();
    float tot = red[0] + red[1] + red[2] + red[3];
    float n = rsqrtf(tot * (1.0f / HDIM) + 1e-6f);
    sv[d] = v * n * sc[d];
    __syncthreads();
    int j = d >> 1, r = d & 1;
    const float* p = pe + (size_t)t * 256 + j * 4 + r * 2;
    buf[d] = p[0] * sv[2 * j] + p[1] * sv[2 * j + 1];
}

// ---------------- K4: flash attention (QT=64, KT=64, HD=128) ----------------
#define ATTN_SMEM_FLOATS (128*68 + 128*68 + 64*68 + 64*132)
__global__ __launch_bounds__(256, 1) void k_attn() {
    extern __shared__ __align__(16) float smf[];
    float* sQT = smf;                    // [128][68] transposed
    float* sKT = sQT + 128 * 68;         // [128][68] transposed
    float* sP  = sKT + 128 * 68;         // [64][68]
    float* sV  = sP + 64 * 68;           // [64][132]
    int head = blockIdx.y;
    int qt0 = blockIdx.x * 64;
    int tid = threadIdx.x;
    const float* Qg = g_q + (size_t)head * LQ * HDIM;
    const float* Kg = g_k + (size_t)head * LQ * HDIM;
    const float* Vg = g_v + (size_t)head * LQ * HDIM;

    // load Q tile transposed
    {
        int c = tid >> 2, d0 = (tid & 3) * 32;
        const float* src = Qg + (size_t)(qt0 + c) * HDIM + d0;
        #pragma unroll
        for (int u = 0; u < 8; ++u) {
            float4 v = *(const float4*)(src + 4 * u);
            sQT[(d0 + 4 * u + 0) * 68 + c] = v.x;
            sQT[(d0 + 4 * u + 1) * 68 + c] = v.y;
            sQT[(d0 + 4 * u + 2) * 68 + c] = v.z;
            sQT[(d0 + 4 * u + 3) * 68 + c] = v.w;
        }
    }

    int rq = (tid >> 4) * 4;   // 4 query rows per thread
    int ck = (tid & 15) * 4;   // 4 key cols per thread (S phase)
    int dd = (tid & 15) * 4;   // dims dd..dd+3 and 64+dd..64+dd+3 (O phase)

    float m_i[4], l_i[4], o[4][8];
    #pragma unroll
    for (int i = 0; i < 4; i++) {
        m_i[i] = -INFINITY; l_i[i] = 0.f;
        #pragma unroll
        for (int j = 0; j < 8; j++) o[i][j] = 0.f;
    }
    const float scale = 0.08838834764831845f;  // 128^-0.5

    for (int kt0 = 0; kt0 < LQ; kt0 += 64) {
        __syncthreads();  // covers Q-load visibility and prior-iter sP/sV reads
        {
            int c = tid >> 2, d0 = (tid & 3) * 32;
            const float* srck = Kg + (size_t)(kt0 + c) * HDIM + d0;
            const float* srcv = Vg + (size_t)(kt0 + c) * HDIM + d0;
            #pragma unroll
            for (int u = 0; u < 8; ++u) {
                float4 kv = *(const float4*)(srck + 4 * u);
                sKT[(d0 + 4 * u + 0) * 68 + c] = kv.x;
                sKT[(d0 + 4 * u + 1) * 68 + c] = kv.y;
                sKT[(d0 + 4 * u + 2) * 68 + c] = kv.z;
                sKT[(d0 + 4 * u + 3) * 68 + c] = kv.w;
                *(float4*)&sV[c * 132 + d0 + 4 * u] = *(const float4*)(srcv + 4 * u);
            }
        }
        __syncthreads();

        // S = Q K^T (4x4 per thread)
        float s[4][4];
        #pragma unroll
        for (int i = 0; i < 4; i++)
            #pragma unroll
            for (int j = 0; j < 4; j++) s[i][j] = 0.f;
        #pragma unroll 4
        for (int k = 0; k < HDIM; k++) {
            float4 qv = *(const float4*)&sQT[k * 68 + rq];
            float4 kv = *(const float4*)&sKT[k * 68 + ck];
            float qa[4] = {qv.x, qv.y, qv.z, qv.w};
            float ka[4] = {kv.x, kv.y, kv.z, kv.w};
            #pragma unroll
            for (int i = 0; i < 4; i++)
                #pragma unroll
                for (int j = 0; j < 4; j++)
                    s[i][j] = fmaf(qa[i], ka[j], s[i][j]);
        }

        // online softmax update, write P
        #pragma unroll
        for (int i = 0; i < 4; i++) {
            float s0 = s[i][0] * scale, s1 = s[i][1] * scale;
            float s2 = s[i][2] * scale, s3 = s[i][3] * scale;
            float tm = fmaxf(fmaxf(s0, s1), fmaxf(s2, s3));
            #pragma unroll
            for (int off = 8; off > 0; off >>= 1)
                tm = fmaxf(tm, __shfl_xor_sync(0xffffffffu, tm, off));
            float newm = fmaxf(m_i[i], tm);
            float corr = __expf(m_i[i] - newm);
            float p0 = __expf(s0 - newm), p1 = __expf(s1 - newm);
            float p2 = __expf(s2 - newm), p3 = __expf(s3 - newm);
            float ls = p0 + p1 + p2 + p3;
            #pragma unroll
            for (int off = 8; off > 0; off >>= 1)
                ls += __shfl_xor_sync(0xffffffffu, ls, off);
            l_i[i] = l_i[i] * corr + ls;
            m_i[i] = newm;
            #pragma unroll
            for (int j = 0; j < 8; j++) o[i][j] *= corr;
            sP[(rq + i) * 68 + ck + 0] = p0;
            sP[(rq + i) * 68 + ck + 1] = p1;
            sP[(rq + i) * 68 + ck + 2] = p2;
            sP[(rq + i) * 68 + ck + 3] = p3;
        }
        __syncthreads();

        // O += P @ V
        #pragma unroll 2
        for (int c = 0; c < 64; c++) {
            float4 v0 = *(const float4*)&sV[c * 132 + dd];
            float4 v1 = *(const float4*)&sV[c * 132 + 64 + dd];
            #pragma unroll
            for (int i = 0; i < 4; i++) {
                float p = sP[(rq + i) * 68 + c];
                o[i][0] = fmaf(p, v0.x, o[i][0]);
                o[i][1] = fmaf(p, v0.y, o[i][1]);
                o[i][2] = fmaf(p, v0.z, o[i][2]);
                o[i][3] = fmaf(p, v0.w, o[i][3]);
                o[i][4] = fmaf(p, v1.x, o[i][4]);
                o[i][5] = fmaf(p, v1.y, o[i][5]);
                o[i][6] = fmaf(p, v1.z, o[i][6]);
                o[i][7] = fmaf(p, v1.w, o[i][7]);
            }
        }
    }

    #pragma unroll
    for (int i = 0; i < 4; i++) {
        float inv = 1.f / l_i[i];
        int t = qt0 + rq + i;
        float* dst = g_scr + (size_t)t * DM + head * HDIM;
        #pragma unroll
        for (int j = 0; j < 4; j++) {
            dst[dd + j] = o[i][j] * inv;
            dst[64 + dd + j] = o[i][4 + j] * inv;
        }
    }
}

// ---------------- K5: GEMM2 out = x + gate * (g_scr @ w2 + b2) ----------------
__global__ __launch_bounds__(256, 2) void k_gemm2(const float* __restrict__ Bm,
                                                  const float* __restrict__ b2,
                                                  const float* __restrict__ x,
                                                  float* __restrict__ out) {
    __shared__ __align__(16) float sA[16][132];
    __shared__ __align__(16) float sB[16][128];
    const int K = DM, N = DMODEL;
    const float* A = g_scr;
    int tid = threadIdx.x;
    int m0 = blockIdx.y * 128, n0 = blockIdx.x * 128;
    int rr2 = (tid >> 4) * 4, cc2 = (tid & 15) * 4;
    float acc[8][8];
    #pragma unroll
    for (int i = 0; i < 8; i++)
        #pragma unroll
        for (int j = 0; j < 8; j++) acc[i][j] = 0.f;

    int ar = tid >> 2, ac = (tid & 3) * 4;
    int br = tid >> 5, bc = (tid & 31) * 4;
    const float* Aptr = A + (size_t)(m0 + ar) * K + ac;
    const float* Bptr = Bm + (size_t)br * N + n0 + bc;

    for (int k0 = 0; k0 < K; k0 += 16) {
        float4 a0 = *(const float4*)(Aptr);
        float4 a1 = *(const float4*)(Aptr + (size_t)64 * K);
        float4 bb0 = *(const float4*)(Bptr);
        float4 bb1 = *(const float4*)(Bptr + (size_t)8 * N);
        sA[ac + 0][ar] = a0.x; sA[ac + 1][ar] = a0.y;
        sA[ac + 2][ar] = a0.z; sA[ac + 3][ar] = a0.w;
        sA[ac + 0][ar + 64] = a1.x; sA[ac + 1][ar + 64] = a1.y;
        sA[ac + 2][ar + 64] = a1.z; sA[ac + 3][ar + 64] = a1.w;
        *(float4*)&sB[br][bc] = bb0;
        *(float4*)&sB[br + 8][bc] = bb1;
        __syncthreads();
        #pragma unroll
        for (int kk = 0; kk < 16; kk++) {
            float a[8], b[8];
            *(float4*)(a) = *(const float4*)&sA[kk][rr2];
            *(float4*)(a + 4) = *(const float4*)&sA[kk][64 + rr2];
            *(float4*)(b) = *(const float4*)&sB[kk][cc2];
            *(float4*)(b + 4) = *(const float4*)&sB[kk][64 + cc2];
            #pragma unroll
            for (int i = 0; i < 8; i++)
                #pragma unroll
                for (int j = 0; j < 8; j++)
                    acc[i][j] = fmaf(a[i], b[j], acc[i][j]);
        }
        __syncthreads();
        Aptr += 16;
        Bptr += (size_t)16 * N;
    }

    #pragma unroll
    for (int i = 0; i < 8; i++) {
        int m = m0 + rr2 + ((i < 4) ? i : 64 + i - 4);
        #pragma unroll
        for (int j = 0; j < 8; j++) {
            int n = n0 + cc2 + ((j < 4) ? j : 64 + j - 4);
            float val = acc[i][j] + b2[n];
            out[(size_t)m * DMODEL + n] =
                x[(size_t)m * DMODEL + n] + g_mod[2 * DMODEL + n] * val;
        }
    }
}

// ---------------- launch ----------------
extern "C" void kernel_launch(void* const* d_in, const int* in_sizes, int n_in,
                              void* d_out, int out_size) {
    (void)in_sizes; (void)n_in; (void)out_size;
    const float* x       = (const float*)d_in[1];
    const float* vec     = (const float*)d_in[2];
    const float* pe      = (const float*)d_in[3];
    const float* mod_w   = (const float*)d_in[4];
    const float* mod_b   = (const float*)d_in[5];
    const float* w1      = (const float*)d_in[6];
    const float* b1      = (const float*)d_in[7];
    const float* w2      = (const float*)d_in[8];
    const float* b2      = (const float*)d_in[9];
    const float* q_scale = (const float*)d_in[10];
    const float* k_scale = (const float*)d_in[11];
    float* out = (float*)d_out;

    cudaFuncSetAttribute(k_attn, cudaFuncAttributeMaxDynamicSharedMemorySize,
                         ATTN_SMEM_FLOATS * (int)sizeof(float));

    k_mod<<<(3 * DMODEL) / 256, 256>>>(vec, mod_w, mod_b);
    k_xmod<<<LQ, 256>>>(x);
    k_gemm1<<<dim3(N1 / 128, LQ / 128), 256>>>(w1, b1);
    k_rmsrope<<<dim3(LQ, NHEAD, 2), 128>>>(pe, q_scale, k_scale);
    k_attn<<<dim3(LQ / 64, NHEAD), 256, ATTN_SMEM_FLOATS * sizeof(float)>>>();
    k_gemm2<<<dim3(DMODEL / 128, LQ / 128), 256>>>(w2, b2, x, out);
}

// round 4
// speedup vs baseline: 1.6468x; 1.6468x over previous
#include <cuda_runtime.h>
#include <cuda_bf16.h>
#include <math.h>
#include <stdint.h>

#define LQ 2048
#define DMODEL 3072
#define NHEAD 24
#define HDIM 128
#define MLPD 12288
#define N1 21504   // 3*D + MLP
#define DM 15360   // D + MLP
#define TD3 9216   // 3*D

// ---------------- scratch (device globals; no allocation allowed) ----------------
__device__ float g_mod[3 * DMODEL];          // [shift | scale | gate]
__device__ float g_q[(size_t)NHEAD * LQ * HDIM];
__device__ float g_k[(size_t)NHEAD * LQ * HDIM];
__device__ float g_v[(size_t)NHEAD * LQ * HDIM];

// split-bf16 operands (hi/lo): A matrices [M][K], B matrices [N][K]
__device__ __align__(128) __nv_bfloat16 g_a1h[(size_t)LQ * DMODEL];
__device__ __align__(128) __nv_bfloat16 g_a1l[(size_t)LQ * DMODEL];
__device__ __align__(128) __nv_bfloat16 g_b1h[(size_t)N1 * DMODEL];
__device__ __align__(128) __nv_bfloat16 g_b1l[(size_t)N1 * DMODEL];
__device__ __align__(128) __nv_bfloat16 g_a2h[(size_t)LQ * DM];
__device__ __align__(128) __nv_bfloat16 g_a2l[(size_t)LQ * DM];
__device__ __align__(128) __nv_bfloat16 g_b2h[(size_t)DMODEL * DM];
__device__ __align__(128) __nv_bfloat16 g_b2l[(size_t)DMODEL * DM];

// ---------------- PTX helpers ----------------
#define CP16(saddr, gptr) \
    asm volatile("cp.async.cg.shared.global [%0], [%1], 16;\n" \
                 :: "r"(saddr), "l"(gptr))
#define CP_COMMIT() asm volatile("cp.async.commit_group;\n")
#define CP_WAIT(n)  asm volatile("cp.async.wait_group %0;\n" :: "n"(n))

__device__ __forceinline__ void mma_bf16(float* c, const uint32_t* a,
                                         uint32_t b0, uint32_t b1) {
    asm volatile(
        "mma.sync.aligned.m16n8k16.row.col.f32.bf16.bf16.f32 "
        "{%0,%1,%2,%3}, {%4,%5,%6,%7}, {%8,%9}, {%0,%1,%2,%3};"
        : "+f"(c[0]), "+f"(c[1]), "+f"(c[2]), "+f"(c[3])
        : "r"(a[0]), "r"(a[1]), "r"(a[2]), "r"(a[3]), "r"(b0), "r"(b1));
}

__device__ __forceinline__ void split_store(__nv_bfloat16* dh, __nv_bfloat16* dl,
                                            size_t idx, float v) {
    __nv_bfloat16 h = __float2bfloat16(v);
    dh[idx] = h;
    dl[idx] = __float2bfloat16(v - __bfloat162float(h));
}

// ---------------- K0: mod = silu(vec) @ mod_w + mod_b ----------------
__global__ void k_mod(const float* __restrict__ vec,
                      const float* __restrict__ mod_w,
                      const float* __restrict__ mod_b) {
    __shared__ float sv[DMODEL];
    for (int i = threadIdx.x; i < DMODEL; i += blockDim.x) {
        float v = vec[i];
        sv[i] = v / (1.0f + expf(-v));
    }
    __syncthreads();
    int col = blockIdx.x * 256 + threadIdx.x;
    float acc = 0.f;
    for (int i = 0; i < DMODEL; ++i)
        acc = fmaf(sv[i], mod_w[(size_t)i * (3 * DMODEL) + col], acc);
    g_mod[col] = acc + mod_b[col];
}

__device__ __forceinline__ float block_sum_256(float v, float* red8) {
    #pragma unroll
    for (int o = 16; o > 0; o >>= 1) v += __shfl_xor_sync(0xffffffffu, v, o);
    if ((threadIdx.x & 31) == 0) red8[threadIdx.x >> 5] = v;
    __syncthreads();
    float t = 0.f;
    #pragma unroll
    for (int i = 0; i < 8; ++i) t += red8[i];
    __syncthreads();
    return t;
}

// ---------------- K1: x_mod -> bf16 hi/lo ----------------
__global__ void k_xmod(const float* __restrict__ x) {
    __shared__ float red8[8];
    int t = blockIdx.x;
    const float* xr = x + (size_t)t * DMODEL;
    float s = 0.f;
    for (int i = threadIdx.x; i < DMODEL; i += 256) s += xr[i];
    float mu = block_sum_256(s, red8) * (1.0f / DMODEL);
    float vs = 0.f;
    for (int i = threadIdx.x; i < DMODEL; i += 256) {
        float d = xr[i] - mu;
        vs += d * d;
    }
    float var = block_sum_256(vs, red8) * (1.0f / DMODEL);
    float rstd = rsqrtf(var + 1e-6f);
    for (int i = threadIdx.x; i < DMODEL; i += 256) {
        float ln = (xr[i] - mu) * rstd;
        float v = g_mod[i] + (1.0f + g_mod[DMODEL + i]) * ln;
        split_store(g_a1h, g_a1l, (size_t)t * DMODEL + i, v);
    }
}

// ---------------- transpose + split: src[R][C] fp32 -> dst[C][R] bf16 hi/lo ----
__global__ void k_cvt_t(const float* __restrict__ src,
                        __nv_bfloat16* __restrict__ dh,
                        __nv_bfloat16* __restrict__ dl, int R, int C) {
    __shared__ float tile[32][33];
    int c0 = blockIdx.x * 32, r0 = blockIdx.y * 32;
    int tx = threadIdx.x, ty = threadIdx.y;
    #pragma unroll
    for (int j = 0; j < 4; j++)
        tile[ty + 8 * j][tx] = src[(size_t)(r0 + ty + 8 * j) * C + c0 + tx];
    __syncthreads();
    #pragma unroll
    for (int j = 0; j < 4; j++) {
        float v = tile[tx][ty + 8 * j];
        int c = c0 + ty + 8 * j, r = r0 + tx;
        split_store(dh, dl, (size_t)c * R + r, v);
    }
}

// ---------------- split-bf16 HMMA GEMM ----------------
// C[m][n] = sum_k A[m][k]B[n][k] via AhBh + AhBl + AlBh  (fp32 accum)
// Block tile 128x128, K-chunk 32, double-buffered cp.async.
// smem per stage: Ah,Al,Bh,Bl each 128 rows x 40 bf16 (pad) = 10240 B.
#define ROWW 40                         // bf16 per smem row (32 + 8 pad)
#define SLAB_W 2560                     // words (u32) per slab = 10240/4
#define STAGE_B 40960                   // bytes per stage (4 slabs)
#define GEMM_SMEM (2 * STAGE_B)

__device__ __forceinline__ void ld_stage_b(
    const __nv_bfloat16* Ah, const __nv_bfloat16* Al,
    const __nv_bfloat16* Bh, const __nv_bfloat16* Bl,
    int K, int m0, int n0, int k0, uint32_t sm, int tid) {
    int row = tid >> 1;
    int cb = (tid & 1) * 32;  // byte col 0 or 32 (row=64B of data)
    uint32_t so = row * (ROWW * 2) + cb;
    const char* ga = (const char*)(Ah + (size_t)(m0 + row) * K + k0) + cb;
    CP16(sm + so, ga); CP16(sm + so + 16, ga + 16);
    const char* gal = (const char*)(Al + (size_t)(m0 + row) * K + k0) + cb;
    CP16(sm + 10240 + so, gal); CP16(sm + 10240 + so + 16, gal + 16);
    const char* gb = (const char*)(Bh + (size_t)(n0 + row) * K + k0) + cb;
    CP16(sm + 20480 + so, gb); CP16(sm + 20480 + so + 16, gb + 16);
    const char* gbl = (const char*)(Bl + (size_t)(n0 + row) * K + k0) + cb;
    CP16(sm + 30720 + so, gbl); CP16(sm + 30720 + so + 16, gbl + 16);
}

// EPI 0: +b1, route qkv(fp32) / gelu -> a2 hi/lo. EPI 1: out = x + gate*(v+b2)
template <int EPI>
__global__ __launch_bounds__(256) void k_gemm_bf(
    const __nv_bfloat16* __restrict__ Ah, const __nv_bfloat16* __restrict__ Al,
    const __nv_bfloat16* __restrict__ Bh, const __nv_bfloat16* __restrict__ Bl,
    int K, const float* __restrict__ bias,
    const float* __restrict__ x, float* __restrict__ out) {
    extern __shared__ __align__(16) char smc[];
    uint32_t sbase;
    asm("{ .reg .u64 t; cvta.to.shared.u64 t, %1; cvt.u32.u64 %0, t; }"
        : "=r"(sbase) : "l"(smc));

    int tid = threadIdx.x;
    int m0 = blockIdx.x * 128;    // m fastest: weight strip hot in L2
    int n0 = blockIdx.y * 128;
    int lane = tid & 31, w = tid >> 5;
    int g = lane >> 2, t4 = lane & 3;
    int wm = w & 3, wn = w >> 2;

    float c[2][8][4];
    #pragma unroll
    for (int mi = 0; mi < 2; mi++)
        #pragma unroll
        for (int ni = 0; ni < 8; ni++)
            #pragma unroll
            for (int cc = 0; cc < 4; cc++) c[mi][ni][cc] = 0.f;

    int nst = K / 32;
    ld_stage_b(Ah, Al, Bh, Bl, K, m0, n0, 0, sbase, tid);
    CP_COMMIT();

    for (int kt = 0; kt < nst; ++kt) {
        if (kt + 1 < nst) {
            ld_stage_b(Ah, Al, Bh, Bl, K, m0, n0, (kt + 1) * 32,
                       sbase + ((kt + 1) & 1) * STAGE_B, tid);
            CP_COMMIT();
            CP_WAIT(1);
        } else {
            CP_WAIT(0);
        }
        __syncthreads();

        const uint32_t* st = (const uint32_t*)(smc + (kt & 1) * STAGE_B);
        const uint32_t* sal = st + SLAB_W;
        const uint32_t* sbh = st + 2 * SLAB_W;
        const uint32_t* sbl = st + 3 * SLAB_W;

        #pragma unroll
        for (int ks = 0; ks < 2; ks++) {
            int kw = ks * 8;  // u32 word offset of this k16 within row
            uint32_t ah[2][4], al[2][4];
            #pragma unroll
            for (int mi = 0; mi < 2; mi++) {
                int r = wm * 32 + mi * 16;
                int bi = (r + g) * 20 + t4 + kw;
                ah[mi][0] = st[bi];        ah[mi][1] = st[bi + 160];
                ah[mi][2] = st[bi + 4];    ah[mi][3] = st[bi + 164];
                al[mi][0] = sal[bi];       al[mi][1] = sal[bi + 160];
                al[mi][2] = sal[bi + 4];   al[mi][3] = sal[bi + 164];
            }
            #pragma unroll
            for (int ni = 0; ni < 8; ni++) {
                int n = wn * 64 + ni * 8;
                int bj = (n + g) * 20 + t4 + kw;
                uint32_t bh0 = sbh[bj], bh1 = sbh[bj + 4];
                uint32_t bl0 = sbl[bj], bl1 = sbl[bj + 4];
                mma_bf16(c[0][ni], ah[0], bh0, bh1);
                mma_bf16(c[1][ni], ah[1], bh0, bh1);
                mma_bf16(c[0][ni], al[0], bh0, bh1);
                mma_bf16(c[1][ni], al[1], bh0, bh1);
                mma_bf16(c[0][ni], ah[0], bl0, bl1);
                mma_bf16(c[1][ni], ah[1], bl0, bl1);
            }
        }
        __syncthreads();
    }

    // ---- epilogue (fragment layout: rows g,g+8; cols 2t,2t+1) ----
    if (EPI == 0) {
        bool is_qkv = n0 < TD3;
        float* qkvdst = nullptr;
        if (is_qkv) {
            int which = n0 / DMODEL;
            int head = (n0 % DMODEL) / HDIM;
            float* base = (which == 0) ? g_q : (which == 1) ? g_k : g_v;
            qkvdst = base + (size_t)head * LQ * HDIM;
        }
        #pragma unroll
        for (int mi = 0; mi < 2; mi++)
            #pragma unroll
            for (int ni = 0; ni < 8; ni++)
                #pragma unroll
                for (int cc = 0; cc < 4; cc++) {
                    int m = m0 + wm * 32 + mi * 16 + g + ((cc >= 2) ? 8 : 0);
                    int dcol = wn * 64 + ni * 8 + 2 * t4 + (cc & 1);
                    int n = n0 + dcol;
                    float val = c[mi][ni][cc] + bias[n];
                    if (is_qkv) {
                        qkvdst[(size_t)m * HDIM + dcol] = val;
                    } else {
                        float x3 = val * val * val;
                        float gv = 0.5f * val *
                            (1.f + tanhf(0.7978845608028654f * (val + 0.044715f * x3)));
                        split_store(g_a2h, g_a2l, (size_t)m * DM + (n - 6144), gv);
                    }
                }
    } else {
        #pragma unroll
        for (int mi = 0; mi < 2; mi++)
            #pragma unroll
            for (int ni = 0; ni < 8; ni++)
                #pragma unroll
                for (int cc = 0; cc < 4; cc++) {
                    int m = m0 + wm * 32 + mi * 16 + g + ((cc >= 2) ? 8 : 0);
                    int n = n0 + wn * 64 + ni * 8 + 2 * t4 + (cc & 1);
                    float val = c[mi][ni][cc] + bias[n];
                    out[(size_t)m * DMODEL + n] =
                        x[(size_t)m * DMODEL + n] + g_mod[2 * DMODEL + n] * val;
                }
    }
}

// ---------------- K3: rms_norm + rope on q and k ----------------
__global__ void k_rmsrope(const float* __restrict__ pe,
                          const float* __restrict__ q_scale,
                          const float* __restrict__ k_scale) {
    int t = blockIdx.x, h = blockIdx.y, qk = blockIdx.z;
    float* buf = (qk == 0 ? g_q : g_k) + ((size_t)h * LQ + t) * HDIM;
    const float* sc = (qk == 0) ? q_scale : k_scale;
    int d = threadIdx.x;
    float v = buf[d];
    __shared__ float red[4];
    __shared__ float sv[HDIM];
    float ss = v * v;
    #pragma unroll
    for (int o = 16; o > 0; o >>= 1) ss += __shfl_xor_sync(0xffffffffu, ss, o);
    if ((d & 31) == 0) red[d >> 5] = ss;
    __syncthreads();
    float tot = red[0] + red[1] + red[2] + red[3];
    float n = rsqrtf(tot * (1.0f / HDIM) + 1e-6f);
    sv[d] = v * n * sc[d];
    __syncthreads();
    int j = d >> 1, r = d & 1;
    const float* p = pe + (size_t)t * 256 + j * 4 + r * 2;
    buf[d] = p[0] * sv[2 * j] + p[1] * sv[2 * j + 1];
}

// ---------------- K4: flash attention (fp32 SIMT), writes a2 hi/lo ----------------
#define ATTN_SMEM_FLOATS (128*68 + 128*68 + 64*68 + 64*132)
__global__ __launch_bounds__(256, 1) void k_attn() {
    extern __shared__ __align__(16) float smf[];
    float* sQT = smf;
    float* sKT = sQT + 128 * 68;
    float* sP  = sKT + 128 * 68;
    float* sV  = sP + 64 * 68;
    int head = blockIdx.y;
    int qt0 = blockIdx.x * 64;
    int tid = threadIdx.x;
    const float* Qg = g_q + (size_t)head * LQ * HDIM;
    const float* Kg = g_k + (size_t)head * LQ * HDIM;
    const float* Vg = g_v + (size_t)head * LQ * HDIM;

    {
        int cidx = tid >> 2, d0 = (tid & 3) * 32;
        const float* src = Qg + (size_t)(qt0 + cidx) * HDIM + d0;
        #pragma unroll
        for (int u = 0; u < 8; ++u) {
            float4 v = *(const float4*)(src + 4 * u);
            sQT[(d0 + 4 * u + 0) * 68 + cidx] = v.x;
            sQT[(d0 + 4 * u + 1) * 68 + cidx] = v.y;
            sQT[(d0 + 4 * u + 2) * 68 + cidx] = v.z;
            sQT[(d0 + 4 * u + 3) * 68 + cidx] = v.w;
        }
    }

    int rq = (tid >> 4) * 4;
    int ck = (tid & 15) * 4;
    int dd = (tid & 15) * 4;

    float m_i[4], l_i[4], o[4][8];
    #pragma unroll
    for (int i = 0; i < 4; i++) {
        m_i[i] = -INFINITY; l_i[i] = 0.f;
        #pragma unroll
        for (int j = 0; j < 8; j++) o[i][j] = 0.f;
    }
    const float scale = 0.08838834764831845f;

    for (int kt0 = 0; kt0 < LQ; kt0 += 64) {
        __syncthreads();
        {
            int cidx = tid >> 2, d0 = (tid & 3) * 32;
            const float* srck = Kg + (size_t)(kt0 + cidx) * HDIM + d0;
            const float* srcv = Vg + (size_t)(kt0 + cidx) * HDIM + d0;
            #pragma unroll
            for (int u = 0; u < 8; ++u) {
                float4 kv = *(const float4*)(srck + 4 * u);
                sKT[(d0 + 4 * u + 0) * 68 + cidx] = kv.x;
                sKT[(d0 + 4 * u + 1) * 68 + cidx] = kv.y;
                sKT[(d0 + 4 * u + 2) * 68 + cidx] = kv.z;
                sKT[(d0 + 4 * u + 3) * 68 + cidx] = kv.w;
                *(float4*)&sV[cidx * 132 + d0 + 4 * u] = *(const float4*)(srcv + 4 * u);
            }
        }
        __syncthreads();

        float s[4][4];
        #pragma unroll
        for (int i = 0; i < 4; i++)
            #pragma unroll
            for (int j = 0; j < 4; j++) s[i][j] = 0.f;
        #pragma unroll 4
        for (int k = 0; k < HDIM; k++) {
            float4 qv = *(const float4*)&sQT[k * 68 + rq];
            float4 kv = *(const float4*)&sKT[k * 68 + ck];
            float qa[4] = {qv.x, qv.y, qv.z, qv.w};
            float ka[4] = {kv.x, kv.y, kv.z, kv.w};
            #pragma unroll
            for (int i = 0; i < 4; i++)
                #pragma unroll
                for (int j = 0; j < 4; j++)
                    s[i][j] = fmaf(qa[i], ka[j], s[i][j]);
        }

        #pragma unroll
        for (int i = 0; i < 4; i++) {
            float s0 = s[i][0] * scale, s1 = s[i][1] * scale;
            float s2 = s[i][2] * scale, s3 = s[i][3] * scale;
            float tm = fmaxf(fmaxf(s0, s1), fmaxf(s2, s3));
            #pragma unroll
            for (int off = 8; off > 0; off >>= 1)
                tm = fmaxf(tm, __shfl_xor_sync(0xffffffffu, tm, off));
            float newm = fmaxf(m_i[i], tm);
            float corr = __expf(m_i[i] - newm);
            float p0 = __expf(s0 - newm), p1 = __expf(s1 - newm);
            float p2 = __expf(s2 - newm), p3 = __expf(s3 - newm);
            float ls = p0 + p1 + p2 + p3;
            #pragma unroll
            for (int off = 8; off > 0; off >>= 1)
                ls += __shfl_xor_sync(0xffffffffu, ls, off);
            l_i[i] = l_i[i] * corr + ls;
            m_i[i] = newm;
            #pragma unroll
            for (int j = 0; j < 8; j++) o[i][j] *= corr;
            sP[(rq + i) * 68 + ck + 0] = p0;
            sP[(rq + i) * 68 + ck + 1] = p1;
            sP[(rq + i) * 68 + ck + 2] = p2;
            sP[(rq + i) * 68 + ck + 3] = p3;
        }
        __syncthreads();

        #pragma unroll 2
        for (int cidx = 0; cidx < 64; cidx++) {
            float4 v0 = *(const float4*)&sV[cidx * 132 + dd];
            float4 v1 = *(const float4*)&sV[cidx * 132 + 64 + dd];
            #pragma unroll
            for (int i = 0; i < 4; i++) {
                float p = sP[(rq + i) * 68 + cidx];
                o[i][0] = fmaf(p, v0.x, o[i][0]);
                o[i][1] = fmaf(p, v0.y, o[i][1]);
                o[i][2] = fmaf(p, v0.z, o[i][2]);
                o[i][3] = fmaf(p, v0.w, o[i][3]);
                o[i][4] = fmaf(p, v1.x, o[i][4]);
                o[i][5] = fmaf(p, v1.y, o[i][5]);
                o[i][6] = fmaf(p, v1.z, o[i][6]);
                o[i][7] = fmaf(p, v1.w, o[i][7]);
            }
        }
    }

    #pragma unroll
    for (int i = 0; i < 4; i++) {
        float inv = 1.f / l_i[i];
        int t = qt0 + rq + i;
        size_t rowb = (size_t)t * DM + head * HDIM;
        #pragma unroll
        for (int j = 0; j < 4; j++) {
            split_store(g_a2h, g_a2l, rowb + dd + j, o[i][j] * inv);
            split_store(g_a2h, g_a2l, rowb + 64 + dd + j, o[i][4 + j] * inv);
        }
    }
}

// ---------------- launch ----------------
extern "C" void kernel_launch(void* const* d_in, const int* in_sizes, int n_in,
                              void* d_out, int out_size) {
    (void)in_sizes; (void)n_in; (void)out_size;
    const float* x       = (const float*)d_in[1];
    const float* vec     = (const float*)d_in[2];
    const float* pe      = (const float*)d_in[3];
    const float* mod_w   = (const float*)d_in[4];
    const float* mod_b   = (const float*)d_in[5];
    const float* w1      = (const float*)d_in[6];
    const float* b1      = (const float*)d_in[7];
    const float* w2      = (const float*)d_in[8];
    const float* b2      = (const float*)d_in[9];
    const float* q_scale = (const float*)d_in[10];
    const float* k_scale = (const float*)d_in[11];
    float* out = (float*)d_out;

    static int attr_done = 0;
    if (!attr_done) {
        cudaFuncSetAttribute(k_attn, cudaFuncAttributeMaxDynamicSharedMemorySize,
                             ATTN_SMEM_FLOATS * (int)sizeof(float));
        cudaFuncSetAttribute(k_gemm_bf<0>,
                             cudaFuncAttributeMaxDynamicSharedMemorySize, GEMM_SMEM);
        cudaFuncSetAttribute(k_gemm_bf<1>,
                             cudaFuncAttributeMaxDynamicSharedMemorySize, GEMM_SMEM);
        attr_done = 1;
    }
    static __nv_bfloat16 *a1h, *a1l, *b1h, *b1l, *a2h, *a2l, *b2h, *b2l;
    if (!a1h) {
        cudaGetSymbolAddress((void**)&a1h, g_a1h);
        cudaGetSymbolAddress((void**)&a1l, g_a1l);
        cudaGetSymbolAddress((void**)&b1h, g_b1h);
        cudaGetSymbolAddress((void**)&b1l, g_b1l);
        cudaGetSymbolAddress((void**)&a2h, g_a2h);
        cudaGetSymbolAddress((void**)&a2l, g_a2l);
        cudaGetSymbolAddress((void**)&b2h, g_b2h);
        cudaGetSymbolAddress((void**)&b2l, g_b2l);
    }

    k_mod<<<(3 * DMODEL) / 256, 256>>>(vec, mod_w, mod_b);
    k_xmod<<<LQ, 256>>>(x);
    // w1 [3072][21504] -> b1h/l [21504][3072]
    k_cvt_t<<<dim3(N1 / 32, DMODEL / 32), dim3(32, 8)>>>(w1, b1h, b1l, DMODEL, N1);
    k_gemm_bf<0><<<dim3(LQ / 128, N1 / 128), 256, GEMM_SMEM>>>(
        a1h, a1l, b1h, b1l, DMODEL, b1, nullptr, nullptr);
    k_rmsrope<<<dim3(LQ, NHEAD, 2), 128>>>(pe, q_scale, k_scale);
    k_attn<<<dim3(LQ / 64, NHEAD), 256, ATTN_SMEM_FLOATS * sizeof(float)>>>();
    // w2 [15360][3072] -> b2h/l [3072][15360]
    k_cvt_t<<<dim3(DMODEL / 32, DM / 32), dim3(32, 8)>>>(w2, b2h, b2l, DM, DMODEL);
    k_gemm_bf<1><<<dim3(LQ / 128, DMODEL / 128), 256, GEMM_SMEM>>>(
        a2h, a2l, b2h, b2l, DM, b2, x, out);
}